// round 15
// baseline (speedup 1.0000x reference)
#include <cuda_runtime.h>

#define NB 8
#define DD 128
#define SS 128
#define MM 16
#define M2 256
#define M3 4096
#define M4 65536

__device__ float g_q  [NB * 512 * M3];
__device__ float g_r  [NB * 768 * M2];
__device__ float g_t  [NB * 512 * MM];
__device__ float g_G3 [4 * NB * SS * M3];
__device__ float g_H2 [6 * NB * SS * M2];
__device__ float g_H1 [4 * NB * SS * MM];
__device__ float g_C0 [DD * SS];
__device__ float g_CB3[4 * 512 * SS];
__device__ float g_CB2[6 * 768 * SS];
__device__ float g_CB1[4 * 512 * SS];

__device__ __forceinline__ void fma2(unsigned long long& d, unsigned long long a,
                                     unsigned long long b) {
    asm("fma.rn.f32x2 %0, %1, %2, %0;" : "+l"(d) : "l"(a), "l"(b));
}
__device__ __forceinline__ unsigned long long pack2(float v) {
    unsigned long long r; unsigned u = __float_as_uint(v);
    asm("mov.b64 %0, {%1, %1};" : "=l"(r) : "r"(u));
    return r;
}
__device__ __forceinline__ float2 unpack2(unsigned long long v) {
    unsigned lo, hi;
    asm("mov.b64 {%0, %1}, %2;" : "=r"(lo), "=r"(hi) : "l"(v));
    float2 f; f.x = __uint_as_float(lo); f.y = __uint_as_float(hi);
    return f;
}

// ---- coef repack + scratch zeroing ----
__global__ void repack_kernel(const float* __restrict__ coefs) {
    int region = blockIdx.y;
    int idx = blockIdx.x * 256 + threadIdx.x;
    if (region == 0) {
        if (idx < DD * SS) {
            int d = idx >> 7, s = idx & 127;
            g_C0[idx] = coefs[(d * 128 + s) * 69 + 0];
        }
    } else if (region == 1) {
        if (idx < 4 * 512 * SS) {
            int B = idx >> 16; int rem = idx & 65535;
            int k = rem >> 7, s = rem & 127;
            int a = k >> 7, d = k & 127;
            g_CB3[idx] = coefs[(d * 128 + s) * 69 + 1 + a * 4 + B];
        }
    } else if (region == 2) {
        if (idx < 6 * 768 * SS) {
            int B = idx / 98304; int rem = idx - B * 98304;
            int k = rem >> 7, s = rem & 127;
            int A = k >> 7, d = k & 127;
            g_CB2[idx] = coefs[(d * 128 + s) * 69 + 17 + A * 6 + B];
        }
    } else if (region == 3) {
        if (idx < 4 * 512 * SS) {
            int B = idx >> 16; int rem = idx & 65535;
            int k = rem >> 7, s = rem & 127;
            int a = k >> 7, d = k & 127;
            g_CB1[idx] = coefs[(d * 128 + s) * 69 + 53 + a * 4 + B];
        }
    } else if (region == 4) {
        if (idx < 16384)
            ((float4*)g_H1)[idx] = make_float4(0.f, 0.f, 0.f, 0.f);
    } else {
        if (idx < 393216)
            ((float4*)g_H2)[idx] = make_float4(0.f, 0.f, 0.f, 0.f);
    }
}

// ---- single-axis pools (q0 accumulated in registers) ----
__global__ void pool1_kernel(const float* __restrict__ x) {
    int nd = blockIdx.x;
    int n = nd >> 7, d = nd & 127;
    const float* xp = x + (size_t)nd * M4;
    __shared__ float slab[16 * 272];
    int t = threadIdx.x;
    float4 acc4[4];
#pragma unroll
    for (int it = 0; it < 4; it++) acc4[it] = make_float4(0.f, 0.f, 0.f, 0.f);
    float* q0row = g_q + (size_t)(n * 512 + 0 * 128 + d) * M3;
    float* q1row = g_q + (size_t)(n * 512 + 1 * 128 + d) * M3;
    float* q2row = g_q + (size_t)(n * 512 + 2 * 128 + d) * M3;
    float* q3row = g_q + (size_t)(n * 512 + 3 * 128 + d) * M3;
    int hi = t >> 4, lo = t & 15;
    for (int i0 = 0; i0 < 16; i0++) {
        const float4* xs4 = (const float4*)(xp + (size_t)i0 * M3);
        __syncthreads();
#pragma unroll
        for (int it = 0; it < 4; it++) {
            int i4 = t + it * 256;
            float4 v = xs4[i4];
            int b = i4 * 4, i1 = b >> 8, i2 = (b >> 4) & 15, i3 = b & 15;
            int p = i1 * 272 + i2 * 17 + i3;
            slab[p] = v.x; slab[p + 1] = v.y; slab[p + 2] = v.z; slab[p + 3] = v.w;
            acc4[it].x += v.x; acc4[it].y += v.y;
            acc4[it].z += v.z; acc4[it].w += v.w;
        }
        __syncthreads();
        float s3 = 0.f, s2 = 0.f, s1 = 0.f;
#pragma unroll
        for (int k = 0; k < 16; k++) {
            s3 += slab[hi * 272 + lo * 17 + k];
            s2 += slab[hi * 272 + k * 17 + lo];
            s1 += slab[k * 272 + hi * 17 + lo];
        }
        q3row[i0 * 256 + t] = s3;
        q2row[i0 * 256 + t] = s2;
        q1row[i0 * 256 + t] = s1;
    }
#pragma unroll
    for (int it = 0; it < 4; it++)
        ((float4*)q0row)[t + it * 256] = acc4[it];
}

// ---- pair + triple pools (q rows staged in padded smem) ----
__global__ void pool2_kernel() {
    extern __shared__ float sl[];
    float* rs = sl + 3 * 4352;
    int nd = blockIdx.x;
    int n = nd >> 7, d = nd & 127;
    int t = threadIdx.x;
#pragma unroll
    for (int j = 0; j < 3; j++) {
        const float4* src = (const float4*)(g_q + (size_t)(n * 512 + (j + 1) * 128 + d) * M3);
        for (int i4 = t; i4 < 1024; i4 += 256) {
            float4 v = src[i4];
            int i = i4 * 4;
            float* dstp = sl + j * 4352 + i + (i >> 4);
            dstp[0] = v.x; dstp[1] = v.y; dstp[2] = v.z; dstp[3] = v.w;
        }
    }
    __syncthreads();
    const int pa[6] = {0, 0, 0, 1, 1, 2};
    const int pb[6] = {1, 2, 3, 2, 3, 3};
    int w0 = t >> 4, w1 = t & 15;
#pragma unroll
    for (int p = 0; p < 6; p++) {
        const float* src = sl + (pb[p] - 1) * 4352;
        int pos = pa[p];
        float sum = 0.f;
#pragma unroll
        for (int k = 0; k < 16; k++) {
            int idx;
            if (pos == 0)      idx = k * 256 + t;
            else if (pos == 1) idx = w0 * 256 + k * 16 + w1;
            else               idx = t * 16 + k;
            sum += src[idx + (idx >> 4)];
        }
        rs[p * 256 + t] = sum;
        g_r[(size_t)(n * 768 + p * 128 + d) * M2 + t] = sum;
    }
    __syncthreads();
    if (t < 64) {
        const int srcp[4] = {3, 4, 5, 5};
        const int tpos[4] = {0, 0, 0, 1};
        int A = t >> 4, w = t & 15;
        const float* rr = rs + srcp[A] * 256;
        float sum = 0.f;
#pragma unroll
        for (int k = 0; k < 16; k++)
            sum += (tpos[A] == 0) ? rr[k * 16 + w] : rr[w * 16 + k];
        g_t[(size_t)(n * 512 + A * 128 + d) * MM + w] = sum;
    }
}

// ---- H1: k-split 16 with atomic accumulation ----
__global__ void h1_kernel() {
    int Bp = blockIdx.x, n = blockIdx.y, kb = blockIdx.z;
    int t = threadIdx.x;                    // 512 threads
    int s = t & 127, wq = t >> 7;
    const float* C = g_CB1 + (size_t)Bp * 512 * SS + s;
    const float* ts = g_t + (size_t)n * 512 * MM;
    float a0 = 0.f, a1 = 0.f, a2 = 0.f, a3 = 0.f;
    int k0 = kb * 32;
#pragma unroll 8
    for (int k = k0; k < k0 + 32; k++) {
        float c = C[(size_t)k * 128];
        float4 tv = *(const float4*)(ts + k * 16 + wq * 4);
        a0 += c * tv.x; a1 += c * tv.y; a2 += c * tv.z; a3 += c * tv.w;
    }
    float* H = g_H1 + (size_t)((Bp * 8 + n) * 128 + s) * MM + wq * 4;
    atomicAdd(H + 0, a0); atomicAdd(H + 1, a1);
    atomicAdd(H + 2, a2); atomicAdd(H + 3, a3);
}

// ---- double-buffered SIMT GEMM core (128 s x 128 px tile) ----
template <int KDIM>
__device__ __forceinline__ void gemm_core(const float* __restrict__ A,
                                          const float* __restrict__ X,
                                          int xrs, int pxb, char* smraw,
                                          unsigned long long (&acc)[8][4]) {
    float* As = (float*)smraw;
    unsigned long long* Xs = (unsigned long long*)(smraw + 16384);
    int t = threadIdx.x;
    int pg = t & 31, sg = t >> 5;
    int r0 = t >> 5, c0 = t & 31;
    int r1 = (t + 256) >> 5;
    const int NC = KDIM / 16;
    float4 av0 = ((const float4*)A)[t];
    float4 av1 = ((const float4*)A)[t + 256];
    float4 xv0 = ((const float4*)(X + (size_t)r0 * xrs + pxb))[c0];
    float4 xv1 = ((const float4*)(X + (size_t)r1 * xrs + pxb))[c0];
    {
        ((float4*)As)[t] = av0; ((float4*)As)[t + 256] = av1;
        ulonglong2* p0 = (ulonglong2*)&Xs[r0 * 128 + c0 * 4];
        p0[0] = make_ulonglong2(pack2(xv0.x), pack2(xv0.y));
        p0[1] = make_ulonglong2(pack2(xv0.z), pack2(xv0.w));
        ulonglong2* p1 = (ulonglong2*)&Xs[r1 * 128 + c0 * 4];
        p1[0] = make_ulonglong2(pack2(xv1.x), pack2(xv1.y));
        p1[1] = make_ulonglong2(pack2(xv1.z), pack2(xv1.w));
    }
    __syncthreads();
    for (int c = 0; c < NC; c++) {
        int cur = c & 1, nxt = cur ^ 1;
        if (c + 1 < NC) {
            int k0 = (c + 1) * 16;
            av0 = ((const float4*)(A + (size_t)k0 * 128))[t];
            av1 = ((const float4*)(A + (size_t)k0 * 128))[t + 256];
            xv0 = ((const float4*)(X + (size_t)(k0 + r0) * xrs + pxb))[c0];
            xv1 = ((const float4*)(X + (size_t)(k0 + r1) * xrs + pxb))[c0];
        }
#pragma unroll
        for (int kk = 0; kk < 16; kk++) {
            unsigned long long a[8];
            const ulonglong2* ap = (const ulonglong2*)&As[cur * 2048 + kk * 128 + sg * 16];
#pragma unroll
            for (int i = 0; i < 4; i++) {
                ulonglong2 v = ap[i];
                a[2 * i] = v.x; a[2 * i + 1] = v.y;
            }
#pragma unroll
            for (int j = 0; j < 4; j++) {
                unsigned long long b = Xs[cur * 2048 + kk * 128 + pg + 32 * j];
#pragma unroll
                for (int i = 0; i < 8; i++) fma2(acc[i][j], a[i], b);
            }
        }
        if (c + 1 < NC) {
            ((float4*)&As[nxt * 2048])[t] = av0;
            ((float4*)&As[nxt * 2048])[t + 256] = av1;
            ulonglong2* p0 = (ulonglong2*)&Xs[nxt * 2048 + r0 * 128 + c0 * 4];
            p0[0] = make_ulonglong2(pack2(xv0.x), pack2(xv0.y));
            p0[1] = make_ulonglong2(pack2(xv0.z), pack2(xv0.w));
            ulonglong2* p1 = (ulonglong2*)&Xs[nxt * 2048 + r1 * 128 + c0 * 4];
            p1[0] = make_ulonglong2(pack2(xv1.x), pack2(xv1.y));
            p1[1] = make_ulonglong2(pack2(xv1.z), pack2(xv1.w));
        }
        __syncthreads();
    }
}

// ---- double-buffered SIMT GEMM core (64 s x 128 px tile) ----
// smem: As float[2][16][64] (8 KB) then Xs ull[2][16][128] (32 KB)
template <int KDIM>
__device__ __forceinline__ void gemm_core64(const float* __restrict__ A, int soff,
                                            const float* __restrict__ X,
                                            int xrs, int pxb, char* smraw,
                                            unsigned long long (&acc)[4][4]) {
    float* As = (float*)smraw;
    unsigned long long* Xs = (unsigned long long*)(smraw + 8192);
    int t = threadIdx.x;
    int pg = t & 31, sg = t >> 5;
    int ra = t >> 4, ca = t & 15;           // A: thread loads 1 float4
    int r0 = t >> 5, c0 = t & 31;
    int r1 = (t + 256) >> 5;
    const int NC = KDIM / 16;
    float4 av = ((const float4*)(A + (size_t)ra * 128 + soff))[ca];
    float4 xv0 = ((const float4*)(X + (size_t)r0 * xrs + pxb))[c0];
    float4 xv1 = ((const float4*)(X + (size_t)r1 * xrs + pxb))[c0];
    {
        ((float4*)As)[t] = av;
        ulonglong2* p0 = (ulonglong2*)&Xs[r0 * 128 + c0 * 4];
        p0[0] = make_ulonglong2(pack2(xv0.x), pack2(xv0.y));
        p0[1] = make_ulonglong2(pack2(xv0.z), pack2(xv0.w));
        ulonglong2* p1 = (ulonglong2*)&Xs[r1 * 128 + c0 * 4];
        p1[0] = make_ulonglong2(pack2(xv1.x), pack2(xv1.y));
        p1[1] = make_ulonglong2(pack2(xv1.z), pack2(xv1.w));
    }
    __syncthreads();
    for (int c = 0; c < NC; c++) {
        int cur = c & 1, nxt = cur ^ 1;
        if (c + 1 < NC) {
            int k0 = (c + 1) * 16;
            av = ((const float4*)(A + (size_t)(k0 + ra) * 128 + soff))[ca];
            xv0 = ((const float4*)(X + (size_t)(k0 + r0) * xrs + pxb))[c0];
            xv1 = ((const float4*)(X + (size_t)(k0 + r1) * xrs + pxb))[c0];
        }
#pragma unroll
        for (int kk = 0; kk < 16; kk++) {
            unsigned long long a[4];
            const ulonglong2* ap = (const ulonglong2*)&As[cur * 1024 + kk * 64 + sg * 8];
#pragma unroll
            for (int i = 0; i < 2; i++) {
                ulonglong2 v = ap[i];
                a[2 * i] = v.x; a[2 * i + 1] = v.y;
            }
#pragma unroll
            for (int j = 0; j < 4; j++) {
                unsigned long long b = Xs[cur * 2048 + kk * 128 + pg + 32 * j];
#pragma unroll
                for (int i = 0; i < 4; i++) fma2(acc[i][j], a[i], b);
            }
        }
        if (c + 1 < NC) {
            ((float4*)&As[nxt * 1024])[t] = av;
            ulonglong2* p0 = (ulonglong2*)&Xs[nxt * 2048 + r0 * 128 + c0 * 4];
            p0[0] = make_ulonglong2(pack2(xv0.x), pack2(xv0.y));
            p0[1] = make_ulonglong2(pack2(xv0.z), pack2(xv0.w));
            ulonglong2* p1 = (ulonglong2*)&Xs[nxt * 2048 + r1 * 128 + c0 * 4];
            p1[0] = make_ulonglong2(pack2(xv1.x), pack2(xv1.y));
            p1[1] = make_ulonglong2(pack2(xv1.z), pack2(xv1.w));
        }
        __syncthreads();
    }
}

// ---- H2 GEMM (K=768, k-split x3, atomic accumulate) ----
__global__ void __launch_bounds__(256, 2) h2_gemm_kernel() {
    extern __shared__ char sm[];
    int B = blockIdx.z / 3, ks = blockIdx.z % 3;
    int n = blockIdx.y;
    int u_base = blockIdx.x * 128;
    unsigned long long acc[8][4];
#pragma unroll
    for (int i = 0; i < 8; i++)
#pragma unroll
        for (int j = 0; j < 4; j++) acc[i][j] = 0ull;
    gemm_core<256>(g_CB2 + (size_t)B * 98304 + (size_t)ks * 256 * 128,
                   g_r + (size_t)n * 768 * M2 + (size_t)ks * 256 * M2,
                   M2, u_base, sm, acc);
    int t = threadIdx.x, pg = t & 31, sg = t >> 5;
    float* Y = g_H2 + (size_t)(B * 8 + n) * SS * M2;
#pragma unroll
    for (int i = 0; i < 8; i++) {
        int s0 = sg * 16 + 2 * i;
#pragma unroll
        for (int j = 0; j < 4; j++) {
            float2 v = unpack2(acc[i][j]);
            int u = u_base + pg + 32 * j;
            atomicAdd(&Y[(size_t)s0 * M2 + u], v.x);
            atomicAdd(&Y[(size_t)(s0 + 1) * M2 + u], v.y);
        }
    }
}

// ---- H3 GEMM (K=512, 64s x 128px tiles) + fold ----
__global__ void __launch_bounds__(256, 3) h3_gemm_kernel(const float* __restrict__ bias) {
    extern __shared__ char sm[];
    int B = blockIdx.z >> 1, sh = blockIdx.z & 1;
    int n = blockIdx.y;
    int u_base = blockIdx.x * 128;
    int soff = sh * 64;
    unsigned long long acc[4][4];
#pragma unroll
    for (int i = 0; i < 4; i++)
#pragma unroll
        for (int j = 0; j < 4; j++) acc[i][j] = 0ull;
    gemm_core64<512>(g_CB3 + (size_t)B * 512 * SS, soff,
                     g_q + (size_t)n * 512 * M3, M3, u_base, sm, acc);
    int t = threadIdx.x, pg = t & 31, sg = t >> 5;
    int v0 = u_base >> 8;
    int v1b = (u_base >> 4) & 15;
    int v2 = pg & 15, v1l = pg >> 4;
    float* Y = g_G3 + (size_t)(B * 8 + n) * SS * M3;
    const float* H2_0 = g_H2 + (size_t)(0 * 8 + n) * SS * M2;
    const float* H2_1 = g_H2 + (size_t)(1 * 8 + n) * SS * M2;
    const float* H2_2 = g_H2 + (size_t)(2 * 8 + n) * SS * M2;
    const float* H2_3 = g_H2 + (size_t)(3 * 8 + n) * SS * M2;
    const float* H2_4 = g_H2 + (size_t)(4 * 8 + n) * SS * M2;
    const float* H2_5 = g_H2 + (size_t)(5 * 8 + n) * SS * M2;
    const float* H1_0 = g_H1 + (size_t)(0 * 8 + n) * SS * MM;
    const float* H1_1 = g_H1 + (size_t)(1 * 8 + n) * SS * MM;
    const float* H1_2 = g_H1 + (size_t)(2 * 8 + n) * SS * MM;
    const float* H1_3 = g_H1 + (size_t)(3 * 8 + n) * SS * MM;
#pragma unroll
    for (int i = 0; i < 4; i++) {
#pragma unroll
        for (int j = 0; j < 4; j++) {
            float2 v = unpack2(acc[i][j]);
            int v1 = v1b + v1l + 2 * j;
            int u = u_base + pg + 32 * j;
#pragma unroll
            for (int h = 0; h < 2; h++) {
                int s = soff + sg * 8 + 2 * i + h;
                float val = h ? v.y : v.x;
                float add = 0.f;
                if (B == 0) {
                    add = H2_0[s * M2 + v0 * 16 + v1] + H2_1[s * M2 + v0 * 16 + v2]
                        + H2_3[s * M2 + v1 * 16 + v2]
                        + H1_0[s * MM + v0] + H1_1[s * MM + v1] + H1_2[s * MM + v2]
                        + bias[s];
                } else if (B == 1) {
                    add = H2_2[s * M2 + v0 * 16 + v2] + H2_4[s * M2 + v1 * 16 + v2]
                        + H1_3[s * MM + v2];
                } else if (B == 2) {
                    add = H2_5[s * M2 + v1 * 16 + v2];
                }
                Y[(size_t)s * M3 + u] = val + add;
            }
        }
    }
}

// ---- main GEMM (K=128) + 4-field G3 fold ----
__global__ void __launch_bounds__(256, 2) main_gemm_kernel(const float* __restrict__ x,
                                                           float* __restrict__ out) {
    extern __shared__ char sm[];
    int n = blockIdx.y;
    int px_base = blockIdx.x * 128;
    unsigned long long acc[8][4];
#pragma unroll
    for (int i = 0; i < 8; i++)
#pragma unroll
        for (int j = 0; j < 4; j++) acc[i][j] = 0ull;
    gemm_core<128>(g_C0, x + (size_t)n * DD * M4, M4, px_base, sm, acc);
    int t = threadIdx.x, pg = t & 31, sg = t >> 5;
    int i0 = px_base >> 12;
    int i1 = (px_base >> 8) & 15;
    int i2b = (px_base >> 4) & 15;
    int i3 = pg & 15, i2l = pg >> 4;
    const float* G0 = g_G3 + (size_t)(0 * 8 + n) * SS * M3;
    const float* G1 = g_G3 + (size_t)(1 * 8 + n) * SS * M3;
    const float* G2 = g_G3 + (size_t)(2 * 8 + n) * SS * M3;
    const float* G3p = g_G3 + (size_t)(3 * 8 + n) * SS * M3;
    int u1 = i0 * 256 + i1 * 16 + i3;
#pragma unroll
    for (int i = 0; i < 8; i++) {
        int s0 = sg * 16 + 2 * i;
#pragma unroll
        for (int j = 0; j < 4; j++) {
            float2 v = unpack2(acc[i][j]);
            int i2 = i2b + i2l + 2 * j;
            int u0 = i0 * 256 + i1 * 16 + i2;
            int u2 = i0 * 256 + i2 * 16 + i3;
            int u3 = i1 * 256 + i2 * 16 + i3;
            int px = px_base + pg + 32 * j;
            float r0 = v.x + G0[(size_t)s0 * M3 + u0] + G1[(size_t)s0 * M3 + u1]
                           + G2[(size_t)s0 * M3 + u2] + G3p[(size_t)s0 * M3 + u3];
            float r1 = v.y + G0[(size_t)(s0 + 1) * M3 + u0] + G1[(size_t)(s0 + 1) * M3 + u1]
                           + G2[(size_t)(s0 + 1) * M3 + u2] + G3p[(size_t)(s0 + 1) * M3 + u3];
            out[(size_t)(n * 128 + s0) * M4 + px] = r0;
            out[(size_t)(n * 128 + s0 + 1) * M4 + px] = r1;
        }
    }
}

// ---- launch ----
extern "C" void kernel_launch(void* const* d_in, const int* in_sizes, int n_in,
                              void* d_out, int out_size) {
    const float* x     = (const float*)d_in[0];
    const float* coefs = (const float*)d_in[1];
    const float* bias  = (const float*)d_in[2];
    float* out = (float*)d_out;

    cudaFuncSetAttribute(pool2_kernel,     cudaFuncAttributeMaxDynamicSharedMemorySize, 58368);
    cudaFuncSetAttribute(h2_gemm_kernel,   cudaFuncAttributeMaxDynamicSharedMemorySize, 49152);
    cudaFuncSetAttribute(h3_gemm_kernel,   cudaFuncAttributeMaxDynamicSharedMemorySize, 40960);
    cudaFuncSetAttribute(main_gemm_kernel, cudaFuncAttributeMaxDynamicSharedMemorySize, 49152);

    repack_kernel<<<dim3(2304, 6), 256>>>(coefs);
    pool1_kernel<<<NB * DD, 256>>>(x);
    pool2_kernel<<<NB * DD, 256, 58368>>>();
    h1_kernel<<<dim3(4, NB, 16), 512>>>();
    h2_gemm_kernel<<<dim3(M2 / 128, NB, 18), 256, 49152>>>();
    h3_gemm_kernel<<<dim3(M3 / 128, NB, 8), 256, 40960>>>(bias);
    main_gemm_kernel<<<dim3(M4 / 128, NB), 256, 49152>>>(x, out);
}

// round 16
// speedup vs baseline: 1.0288x; 1.0288x over previous
#include <cuda_runtime.h>

#define NB 8
#define DD 128
#define SS 128
#define MM 16
#define M2 256
#define M3 4096
#define M4 65536

__device__ float g_q  [NB * 512 * M3];
__device__ float g_r  [NB * 768 * M2];
__device__ float g_t  [NB * 512 * MM];
__device__ float g_G3 [4 * NB * SS * M3];
__device__ float g_H2 [6 * NB * SS * M2];
__device__ float g_H1 [4 * NB * SS * MM];
__device__ float g_C0 [DD * SS];
__device__ float g_CB3[4 * 512 * SS];
__device__ float g_CB2[6 * 768 * SS];
__device__ float g_CB1[4 * 512 * SS];

__device__ __forceinline__ void fma2(unsigned long long& d, unsigned long long a,
                                     unsigned long long b) {
    asm("fma.rn.f32x2 %0, %1, %2, %0;" : "+l"(d) : "l"(a), "l"(b));
}
__device__ __forceinline__ unsigned long long pack2(float v) {
    unsigned long long r; unsigned u = __float_as_uint(v);
    asm("mov.b64 %0, {%1, %1};" : "=l"(r) : "r"(u));
    return r;
}
__device__ __forceinline__ float2 unpack2(unsigned long long v) {
    unsigned lo, hi;
    asm("mov.b64 {%0, %1}, %2;" : "=r"(lo), "=r"(hi) : "l"(v));
    float2 f; f.x = __uint_as_float(lo); f.y = __uint_as_float(hi);
    return f;
}

// ---- coef repack + scratch zeroing ----
__global__ void repack_kernel(const float* __restrict__ coefs) {
    int region = blockIdx.y;
    int idx = blockIdx.x * 256 + threadIdx.x;
    if (region == 0) {
        if (idx < DD * SS) {
            int d = idx >> 7, s = idx & 127;
            g_C0[idx] = coefs[(d * 128 + s) * 69 + 0];
        }
    } else if (region == 1) {
        if (idx < 4 * 512 * SS) {
            int B = idx >> 16; int rem = idx & 65535;
            int k = rem >> 7, s = rem & 127;
            int a = k >> 7, d = k & 127;
            g_CB3[idx] = coefs[(d * 128 + s) * 69 + 1 + a * 4 + B];
        }
    } else if (region == 2) {
        if (idx < 6 * 768 * SS) {
            int B = idx / 98304; int rem = idx - B * 98304;
            int k = rem >> 7, s = rem & 127;
            int A = k >> 7, d = k & 127;
            g_CB2[idx] = coefs[(d * 128 + s) * 69 + 17 + A * 6 + B];
        }
    } else if (region == 3) {
        if (idx < 4 * 512 * SS) {
            int B = idx >> 16; int rem = idx & 65535;
            int k = rem >> 7, s = rem & 127;
            int a = k >> 7, d = k & 127;
            g_CB1[idx] = coefs[(d * 128 + s) * 69 + 53 + a * 4 + B];
        }
    } else if (region == 4) {
        if (idx < 16384)
            ((float4*)g_H1)[idx] = make_float4(0.f, 0.f, 0.f, 0.f);
    } else {
        if (idx < 393216)
            ((float4*)g_H2)[idx] = make_float4(0.f, 0.f, 0.f, 0.f);
    }
}

// ---- single-axis pools (q0 accumulated in registers) ----
__global__ void pool1_kernel(const float* __restrict__ x) {
    int nd = blockIdx.x;
    int n = nd >> 7, d = nd & 127;
    const float* xp = x + (size_t)nd * M4;
    __shared__ float slab[16 * 272];
    int t = threadIdx.x;
    float4 acc4[4];
#pragma unroll
    for (int it = 0; it < 4; it++) acc4[it] = make_float4(0.f, 0.f, 0.f, 0.f);
    float* q0row = g_q + (size_t)(n * 512 + 0 * 128 + d) * M3;
    float* q1row = g_q + (size_t)(n * 512 + 1 * 128 + d) * M3;
    float* q2row = g_q + (size_t)(n * 512 + 2 * 128 + d) * M3;
    float* q3row = g_q + (size_t)(n * 512 + 3 * 128 + d) * M3;
    int hi = t >> 4, lo = t & 15;
    for (int i0 = 0; i0 < 16; i0++) {
        const float4* xs4 = (const float4*)(xp + (size_t)i0 * M3);
        __syncthreads();
#pragma unroll
        for (int it = 0; it < 4; it++) {
            int i4 = t + it * 256;
            float4 v = xs4[i4];
            int b = i4 * 4, i1 = b >> 8, i2 = (b >> 4) & 15, i3 = b & 15;
            int p = i1 * 272 + i2 * 17 + i3;
            slab[p] = v.x; slab[p + 1] = v.y; slab[p + 2] = v.z; slab[p + 3] = v.w;
            acc4[it].x += v.x; acc4[it].y += v.y;
            acc4[it].z += v.z; acc4[it].w += v.w;
        }
        __syncthreads();
        float s3 = 0.f, s2 = 0.f, s1 = 0.f;
#pragma unroll
        for (int k = 0; k < 16; k++) {
            s3 += slab[hi * 272 + lo * 17 + k];
            s2 += slab[hi * 272 + k * 17 + lo];
            s1 += slab[k * 272 + hi * 17 + lo];
        }
        q3row[i0 * 256 + t] = s3;
        q2row[i0 * 256 + t] = s2;
        q1row[i0 * 256 + t] = s1;
    }
#pragma unroll
    for (int it = 0; it < 4; it++)
        ((float4*)q0row)[t + it * 256] = acc4[it];
}

// ---- pair + triple pools (q rows staged in padded smem) ----
__global__ void pool2_kernel() {
    extern __shared__ float sl[];
    float* rs = sl + 3 * 4352;
    int nd = blockIdx.x;
    int n = nd >> 7, d = nd & 127;
    int t = threadIdx.x;
#pragma unroll
    for (int j = 0; j < 3; j++) {
        const float4* src = (const float4*)(g_q + (size_t)(n * 512 + (j + 1) * 128 + d) * M3);
        for (int i4 = t; i4 < 1024; i4 += 256) {
            float4 v = src[i4];
            int i = i4 * 4;
            float* dstp = sl + j * 4352 + i + (i >> 4);
            dstp[0] = v.x; dstp[1] = v.y; dstp[2] = v.z; dstp[3] = v.w;
        }
    }
    __syncthreads();
    const int pa[6] = {0, 0, 0, 1, 1, 2};
    const int pb[6] = {1, 2, 3, 2, 3, 3};
    int w0 = t >> 4, w1 = t & 15;
#pragma unroll
    for (int p = 0; p < 6; p++) {
        const float* src = sl + (pb[p] - 1) * 4352;
        int pos = pa[p];
        float sum = 0.f;
#pragma unroll
        for (int k = 0; k < 16; k++) {
            int idx;
            if (pos == 0)      idx = k * 256 + t;
            else if (pos == 1) idx = w0 * 256 + k * 16 + w1;
            else               idx = t * 16 + k;
            sum += src[idx + (idx >> 4)];
        }
        rs[p * 256 + t] = sum;
        g_r[(size_t)(n * 768 + p * 128 + d) * M2 + t] = sum;
    }
    __syncthreads();
    if (t < 64) {
        const int srcp[4] = {3, 4, 5, 5};
        const int tpos[4] = {0, 0, 0, 1};
        int A = t >> 4, w = t & 15;
        const float* rr = rs + srcp[A] * 256;
        float sum = 0.f;
#pragma unroll
        for (int k = 0; k < 16; k++)
            sum += (tpos[A] == 0) ? rr[k * 16 + w] : rr[w * 16 + k];
        g_t[(size_t)(n * 512 + A * 128 + d) * MM + w] = sum;
    }
}

// ---- H1: k-split 16 with atomic accumulation ----
__global__ void h1_kernel() {
    int Bp = blockIdx.x, n = blockIdx.y, kb = blockIdx.z;
    int t = threadIdx.x;                    // 512 threads
    int s = t & 127, wq = t >> 7;
    const float* C = g_CB1 + (size_t)Bp * 512 * SS + s;
    const float* ts = g_t + (size_t)n * 512 * MM;
    float a0 = 0.f, a1 = 0.f, a2 = 0.f, a3 = 0.f;
    int k0 = kb * 32;
#pragma unroll 8
    for (int k = k0; k < k0 + 32; k++) {
        float c = C[(size_t)k * 128];
        float4 tv = *(const float4*)(ts + k * 16 + wq * 4);
        a0 += c * tv.x; a1 += c * tv.y; a2 += c * tv.z; a3 += c * tv.w;
    }
    float* H = g_H1 + (size_t)((Bp * 8 + n) * 128 + s) * MM + wq * 4;
    atomicAdd(H + 0, a0); atomicAdd(H + 1, a1);
    atomicAdd(H + 2, a2); atomicAdd(H + 3, a3);
}

// ---- double-buffered SIMT GEMM core (128 s x 128 px tile) ----
template <int KDIM>
__device__ __forceinline__ void gemm_core(const float* __restrict__ A,
                                          const float* __restrict__ X,
                                          int xrs, int pxb, char* smraw,
                                          unsigned long long (&acc)[8][4]) {
    float* As = (float*)smraw;
    unsigned long long* Xs = (unsigned long long*)(smraw + 16384);
    int t = threadIdx.x;
    int pg = t & 31, sg = t >> 5;
    int r0 = t >> 5, c0 = t & 31;
    int r1 = (t + 256) >> 5;
    const int NC = KDIM / 16;
    float4 av0 = ((const float4*)A)[t];
    float4 av1 = ((const float4*)A)[t + 256];
    float4 xv0 = ((const float4*)(X + (size_t)r0 * xrs + pxb))[c0];
    float4 xv1 = ((const float4*)(X + (size_t)r1 * xrs + pxb))[c0];
    {
        ((float4*)As)[t] = av0; ((float4*)As)[t + 256] = av1;
        ulonglong2* p0 = (ulonglong2*)&Xs[r0 * 128 + c0 * 4];
        p0[0] = make_ulonglong2(pack2(xv0.x), pack2(xv0.y));
        p0[1] = make_ulonglong2(pack2(xv0.z), pack2(xv0.w));
        ulonglong2* p1 = (ulonglong2*)&Xs[r1 * 128 + c0 * 4];
        p1[0] = make_ulonglong2(pack2(xv1.x), pack2(xv1.y));
        p1[1] = make_ulonglong2(pack2(xv1.z), pack2(xv1.w));
    }
    __syncthreads();
    for (int c = 0; c < NC; c++) {
        int cur = c & 1, nxt = cur ^ 1;
        if (c + 1 < NC) {
            int k0 = (c + 1) * 16;
            av0 = ((const float4*)(A + (size_t)k0 * 128))[t];
            av1 = ((const float4*)(A + (size_t)k0 * 128))[t + 256];
            xv0 = ((const float4*)(X + (size_t)(k0 + r0) * xrs + pxb))[c0];
            xv1 = ((const float4*)(X + (size_t)(k0 + r1) * xrs + pxb))[c0];
        }
#pragma unroll
        for (int kk = 0; kk < 16; kk++) {
            unsigned long long a[8];
            const ulonglong2* ap = (const ulonglong2*)&As[cur * 2048 + kk * 128 + sg * 16];
#pragma unroll
            for (int i = 0; i < 4; i++) {
                ulonglong2 v = ap[i];
                a[2 * i] = v.x; a[2 * i + 1] = v.y;
            }
#pragma unroll
            for (int j = 0; j < 4; j++) {
                unsigned long long b = Xs[cur * 2048 + kk * 128 + pg + 32 * j];
#pragma unroll
                for (int i = 0; i < 8; i++) fma2(acc[i][j], a[i], b);
            }
        }
        if (c + 1 < NC) {
            ((float4*)&As[nxt * 2048])[t] = av0;
            ((float4*)&As[nxt * 2048])[t + 256] = av1;
            ulonglong2* p0 = (ulonglong2*)&Xs[nxt * 2048 + r0 * 128 + c0 * 4];
            p0[0] = make_ulonglong2(pack2(xv0.x), pack2(xv0.y));
            p0[1] = make_ulonglong2(pack2(xv0.z), pack2(xv0.w));
            ulonglong2* p1 = (ulonglong2*)&Xs[nxt * 2048 + r1 * 128 + c0 * 4];
            p1[0] = make_ulonglong2(pack2(xv1.x), pack2(xv1.y));
            p1[1] = make_ulonglong2(pack2(xv1.z), pack2(xv1.w));
        }
        __syncthreads();
    }
}

// ---- H2 GEMM (K=768, k-split x3, atomic accumulate) ----
__global__ void __launch_bounds__(256, 2) h2_gemm_kernel() {
    extern __shared__ char sm[];
    int B = blockIdx.z / 3, ks = blockIdx.z % 3;
    int n = blockIdx.y;
    int u_base = blockIdx.x * 128;
    unsigned long long acc[8][4];
#pragma unroll
    for (int i = 0; i < 8; i++)
#pragma unroll
        for (int j = 0; j < 4; j++) acc[i][j] = 0ull;
    gemm_core<256>(g_CB2 + (size_t)B * 98304 + (size_t)ks * 256 * 128,
                   g_r + (size_t)n * 768 * M2 + (size_t)ks * 256 * M2,
                   M2, u_base, sm, acc);
    int t = threadIdx.x, pg = t & 31, sg = t >> 5;
    float* Y = g_H2 + (size_t)(B * 8 + n) * SS * M2;
#pragma unroll
    for (int i = 0; i < 8; i++) {
        int s0 = sg * 16 + 2 * i;
#pragma unroll
        for (int j = 0; j < 4; j++) {
            float2 v = unpack2(acc[i][j]);
            int u = u_base + pg + 32 * j;
            atomicAdd(&Y[(size_t)s0 * M2 + u], v.x);
            atomicAdd(&Y[(size_t)(s0 + 1) * M2 + u], v.y);
        }
    }
}

// ---- H3 GEMM (K=512, 128x128 tiles) + fold of H2/H1/bias into G3 ----
__global__ void __launch_bounds__(256, 2) h3_gemm_kernel(const float* __restrict__ bias) {
    extern __shared__ char sm[];
    int B = blockIdx.z, n = blockIdx.y;
    int u_base = blockIdx.x * 128;
    unsigned long long acc[8][4];
#pragma unroll
    for (int i = 0; i < 8; i++)
#pragma unroll
        for (int j = 0; j < 4; j++) acc[i][j] = 0ull;
    gemm_core<512>(g_CB3 + (size_t)B * 512 * SS, g_q + (size_t)n * 512 * M3,
                   M3, u_base, sm, acc);
    int t = threadIdx.x, pg = t & 31, sg = t >> 5;
    int v0 = u_base >> 8;
    int v1b = (u_base >> 4) & 15;
    int v2 = pg & 15, v1l = pg >> 4;
    float* Y = g_G3 + (size_t)(B * 8 + n) * SS * M3;
    const float* H2_0 = g_H2 + (size_t)(0 * 8 + n) * SS * M2;
    const float* H2_1 = g_H2 + (size_t)(1 * 8 + n) * SS * M2;
    const float* H2_2 = g_H2 + (size_t)(2 * 8 + n) * SS * M2;
    const float* H2_3 = g_H2 + (size_t)(3 * 8 + n) * SS * M2;
    const float* H2_4 = g_H2 + (size_t)(4 * 8 + n) * SS * M2;
    const float* H2_5 = g_H2 + (size_t)(5 * 8 + n) * SS * M2;
    const float* H1_0 = g_H1 + (size_t)(0 * 8 + n) * SS * MM;
    const float* H1_1 = g_H1 + (size_t)(1 * 8 + n) * SS * MM;
    const float* H1_2 = g_H1 + (size_t)(2 * 8 + n) * SS * MM;
    const float* H1_3 = g_H1 + (size_t)(3 * 8 + n) * SS * MM;
#pragma unroll
    for (int i = 0; i < 8; i++) {
#pragma unroll
        for (int j = 0; j < 4; j++) {
            float2 v = unpack2(acc[i][j]);
            int v1 = v1b + v1l + 2 * j;
            int u = u_base + pg + 32 * j;
#pragma unroll
            for (int h = 0; h < 2; h++) {
                int s = sg * 16 + 2 * i + h;
                float val = h ? v.y : v.x;
                float add = 0.f;
                if (B == 0) {
                    add = H2_0[s * M2 + v0 * 16 + v1] + H2_1[s * M2 + v0 * 16 + v2]
                        + H2_3[s * M2 + v1 * 16 + v2]
                        + H1_0[s * MM + v0] + H1_1[s * MM + v1] + H1_2[s * MM + v2]
                        + bias[s];
                } else if (B == 1) {
                    add = H2_2[s * M2 + v0 * 16 + v2] + H2_4[s * M2 + v1 * 16 + v2]
                        + H1_3[s * MM + v2];
                } else if (B == 2) {
                    add = H2_5[s * M2 + v1 * 16 + v2];
                }
                Y[(size_t)s * M3 + u] = val + add;
            }
        }
    }
}

// ---- main GEMM (K=128) + 4-field G3 fold ----
__global__ void __launch_bounds__(256, 2) main_gemm_kernel(const float* __restrict__ x,
                                                           float* __restrict__ out) {
    extern __shared__ char sm[];
    int n = blockIdx.y;
    int px_base = blockIdx.x * 128;
    unsigned long long acc[8][4];
#pragma unroll
    for (int i = 0; i < 8; i++)
#pragma unroll
        for (int j = 0; j < 4; j++) acc[i][j] = 0ull;
    gemm_core<128>(g_C0, x + (size_t)n * DD * M4, M4, px_base, sm, acc);
    int t = threadIdx.x, pg = t & 31, sg = t >> 5;
    int i0 = px_base >> 12;
    int i1 = (px_base >> 8) & 15;
    int i2b = (px_base >> 4) & 15;
    int i3 = pg & 15, i2l = pg >> 4;
    const float* G0 = g_G3 + (size_t)(0 * 8 + n) * SS * M3;
    const float* G1 = g_G3 + (size_t)(1 * 8 + n) * SS * M3;
    const float* G2 = g_G3 + (size_t)(2 * 8 + n) * SS * M3;
    const float* G3p = g_G3 + (size_t)(3 * 8 + n) * SS * M3;
    int u1 = i0 * 256 + i1 * 16 + i3;
#pragma unroll
    for (int i = 0; i < 8; i++) {
        int s0 = sg * 16 + 2 * i;
#pragma unroll
        for (int j = 0; j < 4; j++) {
            float2 v = unpack2(acc[i][j]);
            int i2 = i2b + i2l + 2 * j;
            int u0 = i0 * 256 + i1 * 16 + i2;
            int u2 = i0 * 256 + i2 * 16 + i3;
            int u3 = i1 * 256 + i2 * 16 + i3;
            int px = px_base + pg + 32 * j;
            float r0 = v.x + G0[(size_t)s0 * M3 + u0] + G1[(size_t)s0 * M3 + u1]
                           + G2[(size_t)s0 * M3 + u2] + G3p[(size_t)s0 * M3 + u3];
            float r1 = v.y + G0[(size_t)(s0 + 1) * M3 + u0] + G1[(size_t)(s0 + 1) * M3 + u1]
                           + G2[(size_t)(s0 + 1) * M3 + u2] + G3p[(size_t)(s0 + 1) * M3 + u3];
            out[(size_t)(n * 128 + s0) * M4 + px] = r0;
            out[(size_t)(n * 128 + s0 + 1) * M4 + px] = r1;
        }
    }
}

// ---- launch ----
extern "C" void kernel_launch(void* const* d_in, const int* in_sizes, int n_in,
                              void* d_out, int out_size) {
    const float* x     = (const float*)d_in[0];
    const float* coefs = (const float*)d_in[1];
    const float* bias  = (const float*)d_in[2];
    float* out = (float*)d_out;

    cudaFuncSetAttribute(pool2_kernel,     cudaFuncAttributeMaxDynamicSharedMemorySize, 58368);
    cudaFuncSetAttribute(h2_gemm_kernel,   cudaFuncAttributeMaxDynamicSharedMemorySize, 49152);
    cudaFuncSetAttribute(h3_gemm_kernel,   cudaFuncAttributeMaxDynamicSharedMemorySize, 49152);
    cudaFuncSetAttribute(main_gemm_kernel, cudaFuncAttributeMaxDynamicSharedMemorySize, 49152);

    repack_kernel<<<dim3(2304, 6), 256>>>(coefs);
    pool1_kernel<<<NB * DD, 256>>>(x);
    pool2_kernel<<<NB * DD, 256, 58368>>>();
    h1_kernel<<<dim3(4, NB, 16), 512>>>();
    h2_gemm_kernel<<<dim3(M2 / 128, NB, 18), 256, 49152>>>();
    h3_gemm_kernel<<<dim3(M3 / 128, NB, 4), 256, 49152>>>(bias);
    main_gemm_kernel<<<dim3(M4 / 128, NB), 256, 49152>>>(x, out);
}